// round 15
// baseline (speedup 1.0000x reference)
#include <cuda_runtime.h>
#include <cuda_bf16.h>

#define G_COUNT 2048
#define NPTS 65536
#define TILE 64
#define BLOCK 64
#define SPLIT 32
#define GPS (G_COUNT / SPLIT)   // 64 gaussians per split
#define NCHUNK (NPTS / 128)     // 512 point-chunks

typedef unsigned long long u64;

__device__ float g_part[SPLIT * NPTS * 3];

__device__ __forceinline__ u64 pk(float a, float b) {
    u64 r; asm("mov.b64 %0,{%1,%2};" : "=l"(r) : "f"(a), "f"(b)); return r;
}
__device__ __forceinline__ void upk(u64 v, float& a, float& b) {
    asm("mov.b64 {%0,%1},%2;" : "=f"(a), "=f"(b) : "l"(v));
}
__device__ __forceinline__ u64 add2(u64 a, u64 b) {
    u64 r; asm("add.rn.f32x2 %0,%1,%2;" : "=l"(r) : "l"(a), "l"(b)); return r;
}
__device__ __forceinline__ u64 mul2(u64 a, u64 b) {
    u64 r; asm("mul.rn.f32x2 %0,%1,%2;" : "=l"(r) : "l"(a), "l"(b)); return r;
}
__device__ __forceinline__ u64 fma2(u64 a, u64 b, u64 c) {
    u64 r; asm("fma.rn.f32x2 %0,%1,%2,%3;" : "=l"(r) : "l"(a), "l"(b), "l"(c)); return r;
}
__device__ __forceinline__ float cosap(float x) {
    float c; asm("cos.approx.f32 %0,%1;" : "=f"(c) : "f"(x)); return c;
}
__device__ __forceinline__ u64 dup(float a) { return pk(a, a); }

// In-block gaussian prep: thread tid preps gaussian (gbeg+tid) straight into
// the smem tile (no prep kernel, no global packed array, no extra launch).
// Layout per gaussian: 14 ulonglong2, every u64 f32x2 with the SAME scalar in
// both halves. K = sqrt(0.5*log2(e)) folded into scales.
//  [0] (-px,-py) [1] (c,s) [2] (K*c*sx, K*s*sx) [3] (K*c*sy, -K*s*sy)
//  [4] (colR,colG) [5] (colB, 0) [6+k] (w_k = fl(2*pi*m_k), coef_k)
__device__ __forceinline__ void prep_into_smem(
    ulonglong2* sm, int g, int tid,
    const float* __restrict__ col, const float* __restrict__ pos,
    const float* __restrict__ scl, const float* __restrict__ rot,
    const float* __restrict__ coef, const int* __restrict__ idx) {
    float th = rot[g];
    float c = cosf(th);
    float s = sinf(th);
    const float K = 0.8493218f;   // sqrt(0.5 * log2(e))
    float sx = scl[2 * g] * K;
    float sy = scl[2 * g + 1] * K;
    ulonglong2* gp = &sm[tid * 14];
    gp[0] = make_ulonglong2(dup(-pos[2 * g]), dup(-pos[2 * g + 1]));
    gp[1] = make_ulonglong2(dup(c), dup(s));
    gp[2] = make_ulonglong2(dup(c * sx), dup(s * sx));
    gp[3] = make_ulonglong2(dup(c * sy), dup(-s * sy));
    gp[4] = make_ulonglong2(dup(col[3 * g]), dup(col[3 * g + 1]));
    gp[5] = make_ulonglong2(dup(col[3 * g + 2]), dup(0.f));
    const float TWO_PI = 6.283185307179586f;  // fl32(2*pi)
#pragma unroll
    for (int k = 0; k < 8; k++)
        gp[6 + k] = make_ulonglong2(dup(TWO_PI * (float)idx[8 * g + k]),
                                    dup(coef[8 * g + k]));
}

__global__ void __launch_bounds__(BLOCK, 12)
main_kernel(const float* __restrict__ x,
            const float* __restrict__ col, const float* __restrict__ pos,
            const float* __restrict__ scl, const float* __restrict__ rot,
            const float* __restrict__ coef, const int* __restrict__ idx) {
    __shared__ ulonglong2 sm[TILE * 14];
    int tid  = threadIdx.x;
    int bid  = blockIdx.x;
    int s    = bid & (SPLIT - 1);
    int chunk = bid >> 5;                  // 128-point chunk
    int n0 = chunk * 128 + tid;
    int n1 = n0 + 64;

    // Prep this split's 64 gaussians directly into smem (one per thread).
    prep_into_smem(sm, s * GPS + tid, tid, col, pos, scl, rot, coef, idx);

    u64 ax2 = pk(x[2 * n0],     x[2 * n1]);
    u64 ay2 = pk(x[2 * n0 + 1], x[2 * n1 + 1]);

    const u64 MAGIC2 = dup(12582912.0f);     // 1.5 * 2^23
    const u64 NEG1_2 = dup(-1.0f);
    const u64 ZERO2  = dup(0.0f);
    const u64 ONE2   = dup(1.0f);
    // Taylor coeffs of 2^{-r} on r in [-0.5,0.5], degree 4 (rel err ~4e-5)
    const u64 EC1 = dup(-0.69314718f);
    const u64 EC2 = dup( 0.24022651f);
    const u64 EC3 = dup(-0.055504109f);
    const u64 EC4 = dup( 0.0096181291f);

    u64 aR = ZERO2, aG = ZERO2, aB = ZERO2;

    __syncthreads();

#pragma unroll 2
    for (int gi = 0; gi < TILE; gi++) {
        const ulonglong2* gp = &sm[gi * 14];
        ulonglong2 q0 = gp[0], q1 = gp[1], q2 = gp[2], q3 = gp[3];
        ulonglong2 q4 = gp[4], q5 = gp[5];

        u64 dx2 = add2(ax2, q0.x);
        u64 dy2 = add2(ay2, q0.y);
        u64 rx2 = fma2(q1.x, dx2, mul2(q1.y, dy2));   // c*dx + s*dy (phase coord)

        // One-time integer-turn reduction of rx: f = rx - round(rx), EXACT,
        // valid because every frequency is an integer number of turns.
        u64 tq2 = add2(rx2, MAGIC2);
        u64 nn2 = fma2(tq2, NEG1_2, MAGIC2);          // -round(rx)
        u64 f2  = add2(rx2, nn2);                     // in [-0.5, 0.5]

        u64 tx2 = fma2(q2.x, dx2, mul2(q2.y, dy2));   // K*sx*rx
        u64 ty2 = fma2(q3.x, dy2, mul2(q3.y, dx2));   // K*sy*ry
        u64 m2  = fma2(ty2, ty2, mul2(tx2, tx2));     // m in [0, ~14.3]

        // env = 2^{-m} on fma+alu pipes (independent of the wave chain)
        u64 etq = add2(m2, MAGIC2);                   // magic: n in low mantissa
        u64 enn = fma2(etq, NEG1_2, MAGIC2);          // -n, exact
        u64 er2 = add2(m2, enn);                      // r = m - n, exact
        u64 ep  = fma2(EC4, er2, EC3);
        ep = fma2(ep, er2, EC2);
        ep = fma2(ep, er2, EC1);
        ep = fma2(ep, er2, ONE2);                     // 2^{-r}
        float tqa, tqb, epa, epb; upk(etq, tqa, tqb); upk(ep, epa, epb);
        unsigned int ea = __float_as_uint(epa) - (__float_as_uint(tqa) << 23);
        unsigned int eb = __float_as_uint(epb) - (__float_as_uint(tqb) << 23);
        u64 env2 = pk(__uint_as_float(ea), __uint_as_float(eb));

        u64 wave2 = ZERO2;
#pragma unroll
        for (int k = 0; k < 8; k++) {
            ulonglong2 wc = gp[6 + k];
            u64 r2 = mul2(wc.x, f2);                  // |arg| <= ~399 rad
            float ra, rb; upk(r2, ra, rb);
            u64 co2 = pk(cosap(ra), cosap(rb));
            wave2 = fma2(wc.y, co2, wave2);
        }

        u64 ew2 = mul2(env2, wave2);
        aR = fma2(ew2, q4.x, aR);
        aG = fma2(ew2, q4.y, aG);
        aB = fma2(ew2, q5.x, aB);
    }

    float r0, r1, g0, g1, b0, b1;
    upk(aR, r0, r1); upk(aG, g0, g1); upk(aB, b0, b1);
    float* p = &g_part[s * NPTS * 3];
    p[3 * n0 + 0] = r0; p[3 * n0 + 1] = g0; p[3 * n0 + 2] = b0;
    p[3 * n1 + 0] = r1; p[3 * n1 + 1] = g1; p[3 * n1 + 2] = b1;
}

__global__ void reduce_kernel(float* __restrict__ out) {
    int i = blockIdx.x * blockDim.x + threadIdx.x;   // float4 index
    if (i >= NPTS * 3 / 4) return;
    const float4* gp = (const float4*)g_part;
    float4 a = gp[i];
#pragma unroll
    for (int sIdx = 1; sIdx < SPLIT; sIdx++) {
        float4 b = gp[sIdx * (NPTS * 3 / 4) + i];
        a.x += b.x; a.y += b.y; a.z += b.z; a.w += b.w;
    }
    ((float4*)out)[i] = a;
}

extern "C" void kernel_launch(void* const* d_in, const int* in_sizes, int n_in,
                              void* d_out, int out_size) {
    const float* x    = (const float*)d_in[0];
    const float* col  = (const float*)d_in[1];
    const float* pos  = (const float*)d_in[2];
    const float* scl  = (const float*)d_in[3];
    const float* rot  = (const float*)d_in[4];
    const float* coef = (const float*)d_in[5];
    const int*   idx  = (const int*)d_in[6];

    main_kernel<<<NCHUNK * SPLIT, BLOCK>>>(x, col, pos, scl, rot, coef, idx);
    reduce_kernel<<<(NPTS * 3 / 4 + 255) / 256, 256>>>((float*)d_out);
}

// round 16
// speedup vs baseline: 1.0545x; 1.0545x over previous
#include <cuda_runtime.h>
#include <cuda_bf16.h>

#define G_COUNT 2048
#define NPTS 65536
#define TILE 64
#define BLOCK 64
#define SPLIT 32
#define GPS (G_COUNT / SPLIT)   // 64 gaussians per split

typedef unsigned long long u64;

// Per-gaussian packed params: 14 ulonglong2; every u64 is f32x2 with the SAME
// scalar in both halves. K = sqrt(0.5*log2(e)) folded into scales.
//  [0] (-px,-py) [1] (c,s) [2] (K*c*sx, K*s*sx) [3] (K*c*sy, -K*s*sy)
//  [4] (colR,colG) [5] (colB, 0) [6+k] (w_k = fl(2*pi*m_k), coef_k)
__device__ ulonglong2 g_packed2[G_COUNT * 14];
__device__ float g_part[SPLIT * NPTS * 3];

__device__ __forceinline__ u64 pk(float a, float b) {
    u64 r; asm("mov.b64 %0,{%1,%2};" : "=l"(r) : "f"(a), "f"(b)); return r;
}
__device__ __forceinline__ void upk(u64 v, float& a, float& b) {
    asm("mov.b64 {%0,%1},%2;" : "=f"(a), "=f"(b) : "l"(v));
}
__device__ __forceinline__ u64 add2(u64 a, u64 b) {
    u64 r; asm("add.rn.f32x2 %0,%1,%2;" : "=l"(r) : "l"(a), "l"(b)); return r;
}
__device__ __forceinline__ u64 mul2(u64 a, u64 b) {
    u64 r; asm("mul.rn.f32x2 %0,%1,%2;" : "=l"(r) : "l"(a), "l"(b)); return r;
}
__device__ __forceinline__ u64 fma2(u64 a, u64 b, u64 c) {
    u64 r; asm("fma.rn.f32x2 %0,%1,%2,%3;" : "=l"(r) : "l"(a), "l"(b), "l"(c)); return r;
}
__device__ __forceinline__ float cosap(float x) {
    float c; asm("cos.approx.f32 %0,%1;" : "=f"(c) : "f"(x)); return c;
}
__device__ __forceinline__ u64 dup(float a) { return pk(a, a); }

__global__ void prep_kernel(const float* __restrict__ col,
                            const float* __restrict__ pos,
                            const float* __restrict__ scl,
                            const float* __restrict__ rot,
                            const float* __restrict__ coef,
                            const int*   __restrict__ idx) {
    int g = blockIdx.x * blockDim.x + threadIdx.x;
    if (g >= G_COUNT) return;
    float th = rot[g];
    float c = cosf(th);
    float s = sinf(th);
    const float K = 0.8493218f;   // sqrt(0.5 * log2(e))
    float sx = scl[2 * g] * K;
    float sy = scl[2 * g + 1] * K;
    ulonglong2* gp = &g_packed2[g * 14];
    gp[0] = make_ulonglong2(dup(-pos[2 * g]), dup(-pos[2 * g + 1]));
    gp[1] = make_ulonglong2(dup(c), dup(s));
    gp[2] = make_ulonglong2(dup(c * sx), dup(s * sx));
    gp[3] = make_ulonglong2(dup(c * sy), dup(-s * sy));
    gp[4] = make_ulonglong2(dup(col[3 * g]), dup(col[3 * g + 1]));
    gp[5] = make_ulonglong2(dup(col[3 * g + 2]), dup(0.f));
    const float TWO_PI = 6.283185307179586f;  // fl32(2*pi)
#pragma unroll
    for (int k = 0; k < 8; k++)
        gp[6 + k] = make_ulonglong2(dup(TWO_PI * (float)idx[8 * g + k]),
                                    dup(coef[8 * g + k]));
}

__global__ void __launch_bounds__(BLOCK, 12)
main_kernel(const float* __restrict__ x) {
    __shared__ ulonglong2 sm[TILE * 14];
    int tid  = threadIdx.x;
    int bid  = blockIdx.x;
    int s    = bid & (SPLIT - 1);
    int chunk = bid >> 5;                  // 128-point chunk
    int n0 = chunk * 128 + tid;
    int n1 = n0 + 64;

    u64 ax2 = pk(x[2 * n0],     x[2 * n1]);
    u64 ay2 = pk(x[2 * n0 + 1], x[2 * n1 + 1]);

    const u64 MAGIC2 = dup(12582912.0f);     // 1.5 * 2^23 (low 9 bits of pattern are 0)
    const u64 NEG1_2 = dup(-1.0f);
    const u64 ZERO2  = dup(0.0f);
    const u64 ONE2   = dup(1.0f);
    // Taylor coeffs of 2^{-r} on r in [-0.5,0.5], degree 4 (rel err ~4e-5)
    const u64 EC1 = dup(-0.69314718f);
    const u64 EC2 = dup( 0.24022651f);
    const u64 EC3 = dup(-0.055504109f);
    const u64 EC4 = dup( 0.0096181291f);

    u64 aR = ZERO2, aG = ZERO2, aB = ZERO2;

    // Single-shot tile load (TILE == GPS): one round, two syncs total.
    int gbeg = s * GPS;
    for (int i = tid; i < TILE * 14; i += BLOCK)
        sm[i] = g_packed2[gbeg * 14 + i];
    __syncthreads();

#pragma unroll 2
    for (int gi = 0; gi < TILE; gi++) {
        const ulonglong2* gp = &sm[gi * 14];
        ulonglong2 q0 = gp[0], q1 = gp[1], q2 = gp[2], q3 = gp[3];
        ulonglong2 q4 = gp[4], q5 = gp[5];

        u64 dx2 = add2(ax2, q0.x);
        u64 dy2 = add2(ay2, q0.y);
        u64 rx2 = fma2(q1.x, dx2, mul2(q1.y, dy2));   // c*dx + s*dy (phase coord)

        // One-time integer-turn reduction of rx: f = rx - round(rx), EXACT,
        // valid because every frequency is an integer number of turns.
        u64 tq2 = add2(rx2, MAGIC2);
        u64 nn2 = fma2(tq2, NEG1_2, MAGIC2);          // -round(rx)
        u64 f2  = add2(rx2, nn2);                     // in [-0.5, 0.5]

        u64 tx2 = fma2(q2.x, dx2, mul2(q2.y, dy2));   // K*sx*rx
        u64 ty2 = fma2(q3.x, dy2, mul2(q3.y, dx2));   // K*sy*ry
        u64 m2  = fma2(ty2, ty2, mul2(tx2, tx2));     // m in [0, ~14.3]

        // env = 2^{-m} on fma+alu pipes (independent of the wave chain)
        u64 etq = add2(m2, MAGIC2);                   // magic: n in low mantissa
        u64 enn = fma2(etq, NEG1_2, MAGIC2);          // -n, exact
        u64 er2 = add2(m2, enn);                      // r = m - n, exact
        u64 ep  = fma2(EC4, er2, EC3);
        ep = fma2(ep, er2, EC2);
        ep = fma2(ep, er2, EC1);
        ep = fma2(ep, er2, ONE2);                     // 2^{-r}
        float tqa, tqb, epa, epb; upk(etq, tqa, tqb); upk(ep, epa, epb);
        unsigned int ea = __float_as_uint(epa) - (__float_as_uint(tqa) << 23);
        unsigned int eb = __float_as_uint(epb) - (__float_as_uint(tqb) << 23);
        u64 env2 = pk(__uint_as_float(ea), __uint_as_float(eb));

        u64 wave2 = ZERO2;
#pragma unroll
        for (int k = 0; k < 8; k++) {
            ulonglong2 wc = gp[6 + k];
            u64 r2 = mul2(wc.x, f2);                  // |arg| <= ~399 rad
            float ra, rb; upk(r2, ra, rb);
            u64 co2 = pk(cosap(ra), cosap(rb));
            wave2 = fma2(wc.y, co2, wave2);
        }

        u64 ew2 = mul2(env2, wave2);
        aR = fma2(ew2, q4.x, aR);
        aG = fma2(ew2, q4.y, aG);
        aB = fma2(ew2, q5.x, aB);
    }

    float r0, r1, g0, g1, b0, b1;
    upk(aR, r0, r1); upk(aG, g0, g1); upk(aB, b0, b1);
    float* p = &g_part[s * NPTS * 3];
    p[3 * n0 + 0] = r0; p[3 * n0 + 1] = g0; p[3 * n0 + 2] = b0;
    p[3 * n1 + 0] = r1; p[3 * n1 + 1] = g1; p[3 * n1 + 2] = b1;
}

__global__ void reduce_kernel(float* __restrict__ out) {
    int i = blockIdx.x * blockDim.x + threadIdx.x;   // float4 index
    if (i >= NPTS * 3 / 4) return;
    const float4* gp = (const float4*)g_part;
    float4 a = gp[i];
#pragma unroll
    for (int sIdx = 1; sIdx < SPLIT; sIdx++) {
        float4 b = gp[sIdx * (NPTS * 3 / 4) + i];
        a.x += b.x; a.y += b.y; a.z += b.z; a.w += b.w;
    }
    ((float4*)out)[i] = a;
}

extern "C" void kernel_launch(void* const* d_in, const int* in_sizes, int n_in,
                              void* d_out, int out_size) {
    const float* x    = (const float*)d_in[0];
    const float* col  = (const float*)d_in[1];
    const float* pos  = (const float*)d_in[2];
    const float* scl  = (const float*)d_in[3];
    const float* rot  = (const float*)d_in[4];
    const float* coef = (const float*)d_in[5];
    const int*   idx  = (const int*)d_in[6];

    prep_kernel<<<32, 64>>>(col, pos, scl, rot, coef, idx);
    main_kernel<<<(NPTS / 128) * SPLIT, BLOCK>>>(x);
    reduce_kernel<<<(NPTS * 3 / 4 + 255) / 256, 256>>>((float*)d_out);
}

// round 17
// speedup vs baseline: 1.0562x; 1.0016x over previous
#include <cuda_runtime.h>
#include <cuda_bf16.h>

#define G_COUNT 2048
#define NPTS 65536
#define TILE 64
#define BLOCK 64
#define SPLIT 32
#define GPS (G_COUNT / SPLIT)   // 64 gaussians per split

typedef unsigned long long u64;

// Per-gaussian packed params: 14 ulonglong2; every u64 is f32x2 with the SAME
// scalar in both halves. K = sqrt(0.5*log2(e)) folded into scales.
//  [0] (-px,-py) [1] (c,s) [2] (K*c*sx, K*s*sx) [3] (K*c*sy, -K*s*sy)
//  [4] (colR,colG) [5] (colB, 0) [6+k] (w_k = fl(2*pi*m_k), coef_k)
__device__ ulonglong2 g_packed2[G_COUNT * 14];
__device__ float g_part[SPLIT * NPTS * 3];

__device__ __forceinline__ u64 pk(float a, float b) {
    u64 r; asm("mov.b64 %0,{%1,%2};" : "=l"(r) : "f"(a), "f"(b)); return r;
}
__device__ __forceinline__ void upk(u64 v, float& a, float& b) {
    asm("mov.b64 {%0,%1},%2;" : "=f"(a), "=f"(b) : "l"(v));
}
__device__ __forceinline__ u64 add2(u64 a, u64 b) {
    u64 r; asm("add.rn.f32x2 %0,%1,%2;" : "=l"(r) : "l"(a), "l"(b)); return r;
}
__device__ __forceinline__ u64 mul2(u64 a, u64 b) {
    u64 r; asm("mul.rn.f32x2 %0,%1,%2;" : "=l"(r) : "l"(a), "l"(b)); return r;
}
__device__ __forceinline__ u64 fma2(u64 a, u64 b, u64 c) {
    u64 r; asm("fma.rn.f32x2 %0,%1,%2,%3;" : "=l"(r) : "l"(a), "l"(b), "l"(c)); return r;
}
__device__ __forceinline__ float cosap(float x) {
    float c; asm("cos.approx.f32 %0,%1;" : "=f"(c) : "f"(x)); return c;
}
__device__ __forceinline__ u64 dup(float a) { return pk(a, a); }

// Parallel prep: one thread per (gaussian, slot) -> 14x the memory-level
// parallelism of the per-gaussian version (prep is DRAM-latency bound).
__global__ void prep_kernel(const float* __restrict__ col,
                            const float* __restrict__ pos,
                            const float* __restrict__ scl,
                            const float* __restrict__ rot,
                            const float* __restrict__ coef,
                            const int*   __restrict__ idx) {
    int i = blockIdx.x * blockDim.x + threadIdx.x;
    if (i >= G_COUNT * 14) return;
    int g    = i / 14;
    int slot = i - g * 14;
    const float K = 0.8493218f;               // sqrt(0.5 * log2(e))
    const float TWO_PI = 6.283185307179586f;  // fl32(2*pi)
    ulonglong2 v;
    if (slot >= 6) {
        int k = slot - 6;
        v = make_ulonglong2(dup(TWO_PI * (float)idx[8 * g + k]),
                            dup(coef[8 * g + k]));
    } else if (slot == 0) {
        v = make_ulonglong2(dup(-pos[2 * g]), dup(-pos[2 * g + 1]));
    } else if (slot == 1) {
        float th = rot[g];
        v = make_ulonglong2(dup(cosf(th)), dup(sinf(th)));
    } else if (slot == 2) {
        float th = rot[g];
        float sx = scl[2 * g] * K;
        v = make_ulonglong2(dup(cosf(th) * sx), dup(sinf(th) * sx));
    } else if (slot == 3) {
        float th = rot[g];
        float sy = scl[2 * g + 1] * K;
        v = make_ulonglong2(dup(cosf(th) * sy), dup(-sinf(th) * sy));
    } else if (slot == 4) {
        v = make_ulonglong2(dup(col[3 * g]), dup(col[3 * g + 1]));
    } else {
        v = make_ulonglong2(dup(col[3 * g + 2]), dup(0.f));
    }
    g_packed2[i] = v;
}

__global__ void __launch_bounds__(BLOCK, 12)
main_kernel(const float* __restrict__ x) {
    __shared__ ulonglong2 sm[TILE * 14];
    int tid  = threadIdx.x;
    int bid  = blockIdx.x;
    int s    = bid & (SPLIT - 1);
    int chunk = bid >> 5;                  // 128-point chunk
    int n0 = chunk * 128 + tid;
    int n1 = n0 + 64;

    u64 ax2 = pk(x[2 * n0],     x[2 * n1]);
    u64 ay2 = pk(x[2 * n0 + 1], x[2 * n1 + 1]);

    const u64 MAGIC2 = dup(12582912.0f);     // 1.5 * 2^23 (low 9 bits of pattern are 0)
    const u64 NEG1_2 = dup(-1.0f);
    const u64 ZERO2  = dup(0.0f);
    const u64 ONE2   = dup(1.0f);
    // Taylor coeffs of 2^{-r} on r in [-0.5,0.5], degree 4 (rel err ~4e-5)
    const u64 EC1 = dup(-0.69314718f);
    const u64 EC2 = dup( 0.24022651f);
    const u64 EC3 = dup(-0.055504109f);
    const u64 EC4 = dup( 0.0096181291f);

    u64 aR = ZERO2, aG = ZERO2, aB = ZERO2;

    // Single-shot tile load (TILE == GPS): one round, two syncs total.
    int gbeg = s * GPS;
    for (int i = tid; i < TILE * 14; i += BLOCK)
        sm[i] = g_packed2[gbeg * 14 + i];
    __syncthreads();

#pragma unroll 2
    for (int gi = 0; gi < TILE; gi++) {
        const ulonglong2* gp = &sm[gi * 14];
        ulonglong2 q0 = gp[0], q1 = gp[1], q2 = gp[2], q3 = gp[3];
        ulonglong2 q4 = gp[4], q5 = gp[5];

        u64 dx2 = add2(ax2, q0.x);
        u64 dy2 = add2(ay2, q0.y);
        u64 rx2 = fma2(q1.x, dx2, mul2(q1.y, dy2));   // c*dx + s*dy (phase coord)

        // One-time integer-turn reduction of rx: f = rx - round(rx), EXACT,
        // valid because every frequency is an integer number of turns.
        u64 tq2 = add2(rx2, MAGIC2);
        u64 nn2 = fma2(tq2, NEG1_2, MAGIC2);          // -round(rx)
        u64 f2  = add2(rx2, nn2);                     // in [-0.5, 0.5]

        u64 tx2 = fma2(q2.x, dx2, mul2(q2.y, dy2));   // K*sx*rx
        u64 ty2 = fma2(q3.x, dy2, mul2(q3.y, dx2));   // K*sy*ry
        u64 m2  = fma2(ty2, ty2, mul2(tx2, tx2));     // m in [0, ~14.3]

        // env = 2^{-m} on fma+alu pipes (independent of the wave chain)
        u64 etq = add2(m2, MAGIC2);                   // magic: n in low mantissa
        u64 enn = fma2(etq, NEG1_2, MAGIC2);          // -n, exact
        u64 er2 = add2(m2, enn);                      // r = m - n, exact
        u64 ep  = fma2(EC4, er2, EC3);
        ep = fma2(ep, er2, EC2);
        ep = fma2(ep, er2, EC1);
        ep = fma2(ep, er2, ONE2);                     // 2^{-r}
        float tqa, tqb, epa, epb; upk(etq, tqa, tqb); upk(ep, epa, epb);
        unsigned int ea = __float_as_uint(epa) - (__float_as_uint(tqa) << 23);
        unsigned int eb = __float_as_uint(epb) - (__float_as_uint(tqb) << 23);
        u64 env2 = pk(__uint_as_float(ea), __uint_as_float(eb));

        u64 wave2 = ZERO2;
#pragma unroll
        for (int k = 0; k < 8; k++) {
            ulonglong2 wc = gp[6 + k];
            u64 r2 = mul2(wc.x, f2);                  // |arg| <= ~399 rad
            float ra, rb; upk(r2, ra, rb);
            u64 co2 = pk(cosap(ra), cosap(rb));
            wave2 = fma2(wc.y, co2, wave2);
        }

        u64 ew2 = mul2(env2, wave2);
        aR = fma2(ew2, q4.x, aR);
        aG = fma2(ew2, q4.y, aG);
        aB = fma2(ew2, q5.x, aB);
    }

    float r0, r1, g0, g1, b0, b1;
    upk(aR, r0, r1); upk(aG, g0, g1); upk(aB, b0, b1);
    float* p = &g_part[s * NPTS * 3];
    p[3 * n0 + 0] = r0; p[3 * n0 + 1] = g0; p[3 * n0 + 2] = b0;
    p[3 * n1 + 0] = r1; p[3 * n1 + 1] = g1; p[3 * n1 + 2] = b1;
}

__global__ void reduce_kernel(float* __restrict__ out) {
    int i = blockIdx.x * blockDim.x + threadIdx.x;   // float4 index
    if (i >= NPTS * 3 / 4) return;
    const float4* gp = (const float4*)g_part;
    float4 a = gp[i];
#pragma unroll
    for (int sIdx = 1; sIdx < SPLIT; sIdx++) {
        float4 b = gp[sIdx * (NPTS * 3 / 4) + i];
        a.x += b.x; a.y += b.y; a.z += b.z; a.w += b.w;
    }
    ((float4*)out)[i] = a;
}

extern "C" void kernel_launch(void* const* d_in, const int* in_sizes, int n_in,
                              void* d_out, int out_size) {
    const float* x    = (const float*)d_in[0];
    const float* col  = (const float*)d_in[1];
    const float* pos  = (const float*)d_in[2];
    const float* scl  = (const float*)d_in[3];
    const float* rot  = (const float*)d_in[4];
    const float* coef = (const float*)d_in[5];
    const int*   idx  = (const int*)d_in[6];

    prep_kernel<<<(G_COUNT * 14 + 127) / 128, 128>>>(col, pos, scl, rot, coef, idx);
    main_kernel<<<(NPTS / 128) * SPLIT, BLOCK>>>(x);
    reduce_kernel<<<(NPTS * 3 / 4 + 255) / 256, 256>>>((float*)d_out);
}